// round 2
// baseline (speedup 1.0000x reference)
#include <cuda_runtime.h>
#include <math.h>
#include <float.h>

#define BATCH 2
#define NCTX  2048
#define DIM   512
#define HEADS 8
#define DHEAD 64
#define KNN   32
#define MDB   131072
#define MROWS (BATCH*NCTX)   // 4096

// scratch (device globals; no allocation allowed)
__device__ float g_q[MROWS * DIM];   // q raw, layout (b, n, h*d)
__device__ float g_o[MROWS * DIM];   // attention output, layout (b, n, h*d)

// ---------------------------------------------------------------------------
// C[M,N] = A[M,K] * B[N,K]^T   (all row-major, M%64==0, N%64==0, K%16==0)
// BM=64, BN=64, BK=16, 256 threads, 4x4 microtile per thread.
// ---------------------------------------------------------------------------
__global__ void sgemm_abt(const float* __restrict__ A,
                          const float* __restrict__ Bm,
                          float* __restrict__ C,
                          int M, int N, int K)
{
    __shared__ __align__(16) float As[16][64];
    __shared__ __align__(16) float Bs[16][64];

    const int t    = threadIdx.x;       // 0..255
    const int tx   = t & 15;            // 0..15
    const int ty   = t >> 4;            // 0..15
    const int row0 = blockIdx.y * 64;
    const int col0 = blockIdx.x * 64;

    const int lrow = t >> 2;            // 0..63
    const int lk4  = (t & 3) * 4;       // 0,4,8,12

    float acc[4][4];
#pragma unroll
    for (int i = 0; i < 4; i++)
#pragma unroll
        for (int j = 0; j < 4; j++) acc[i][j] = 0.f;

    for (int k0 = 0; k0 < K; k0 += 16) {
        float4 av = *(const float4*)(A  + (long)(row0 + lrow) * K + k0 + lk4);
        float4 bv = *(const float4*)(Bm + (long)(col0 + lrow) * K + k0 + lk4);
        As[lk4 + 0][lrow] = av.x; As[lk4 + 1][lrow] = av.y;
        As[lk4 + 2][lrow] = av.z; As[lk4 + 3][lrow] = av.w;
        Bs[lk4 + 0][lrow] = bv.x; Bs[lk4 + 1][lrow] = bv.y;
        Bs[lk4 + 2][lrow] = bv.z; Bs[lk4 + 3][lrow] = bv.w;
        __syncthreads();

#pragma unroll
        for (int kk = 0; kk < 16; kk++) {
            float4 a = *(const float4*)&As[kk][ty * 4];
            float4 b = *(const float4*)&Bs[kk][tx * 4];
            float ar[4] = {a.x, a.y, a.z, a.w};
            float br[4] = {b.x, b.y, b.z, b.w};
#pragma unroll
            for (int i = 0; i < 4; i++)
#pragma unroll
                for (int j = 0; j < 4; j++)
                    acc[i][j] = fmaf(ar[i], br[j], acc[i][j]);
        }
        __syncthreads();
    }

#pragma unroll
    for (int i = 0; i < 4; i++) {
        int r = row0 + ty * 4 + i;
        float4 v = make_float4(acc[i][0], acc[i][1], acc[i][2], acc[i][3]);
        *(float4*)(C + (long)r * N + col0 + tx * 4) = v;
    }
}

// ---------------------------------------------------------------------------
// KNN attention: one warp per query (b, h, n). K=32 neighbors -> lane j owns
// neighbor j's sim/attn. q normalization + exp(scale) folded into q.
// mem_mask arrives as int32 (bool promoted by the harness).
// ---------------------------------------------------------------------------
__global__ void knn_attn(const float* __restrict__ mem_db,
                         const int*   __restrict__ knn_idx,
                         const int*   __restrict__ mem_mask,
                         const float* __restrict__ scale_param)
{
    const unsigned FULL = 0xffffffffu;
    int warp = (blockIdx.x * blockDim.x + threadIdx.x) >> 5;
    int lane = threadIdx.x & 31;
    if (warp >= BATCH * HEADS * NCTX) return;

    int n  = warp % NCTX;
    int bh = warp / NCTX;
    int h  = bh % HEADS;
    int b  = bh / HEADS;

    // q stored (b, n, h*d)
    const float* qp = g_q + ((long)(b * NCTX + n) * DIM) + h * DHEAD;
    float q0 = qp[lane];
    float q1 = qp[lane + 32];

    // L2 norm over d=64
    float ss = q0 * q0 + q1 * q1;
#pragma unroll
    for (int o = 16; o > 0; o >>= 1) ss += __shfl_xor_sync(FULL, ss, o);
    float scale = expf(scale_param[h]);
    float inv = scale / fmaxf(sqrtf(ss), 1e-12f);
    q0 *= inv; q1 *= inv;

    long ib = (long)((b * HEADS + h) * NCTX + n) * KNN;
    int  idx = knn_idx[ib + lane];
    bool msk = mem_mask[ib + lane] != 0;

    const float* db = mem_db + (long)b * MDB * 2 * DHEAD;

    // sim_j = q . k_j  (scaled); lane j keeps sim_j
    float sim = 0.f;
#pragma unroll
    for (int j = 0; j < KNN; j++) {
        int ij = __shfl_sync(FULL, idx, j);
        const float* kp = db + (long)ij * (2 * DHEAD);
        float p = fmaf(q0, kp[lane], q1 * kp[lane + 32]);
#pragma unroll
        for (int o = 16; o > 0; o >>= 1) p += __shfl_xor_sync(FULL, p, o);
        if (lane == j) sim = p;
    }

    sim = msk ? sim : -FLT_MAX;

    // softmax over lanes
    float m = sim;
#pragma unroll
    for (int o = 16; o > 0; o >>= 1) m = fmaxf(m, __shfl_xor_sync(FULL, m, o));
    float p = __expf(sim - m);
    float s = p;
#pragma unroll
    for (int o = 16; o > 0; o >>= 1) s += __shfl_xor_sync(FULL, s, o);
    float attn = p / s;

    // out = sum_j attn_j * v_j
    float o0 = 0.f, o1 = 0.f;
#pragma unroll
    for (int j = 0; j < KNN; j++) {
        float a  = __shfl_sync(FULL, attn, j);
        int   ij = __shfl_sync(FULL, idx, j);
        const float* vp = db + (long)ij * (2 * DHEAD) + DHEAD;
        o0 = fmaf(a, vp[lane], o0);
        o1 = fmaf(a, vp[lane + 32], o1);
    }

    float* op = g_o + ((long)(b * NCTX + n) * DIM) + h * DHEAD;
    op[lane]      = o0;
    op[lane + 32] = o1;
}

// ---------------------------------------------------------------------------
extern "C" void kernel_launch(void* const* d_in, const int* in_sizes, int n_in,
                              void* d_out, int out_size)
{
    const float* x        = (const float*)d_in[0];
    const float* mem_db   = (const float*)d_in[1];
    const int*   knn_idx  = (const int*)d_in[2];
    const int*   mem_mask = (const int*)d_in[3];
    const float* Wq       = (const float*)d_in[4];
    // d_in[5] = Wkv : dead code in the reference, never used
    const float* Wout     = (const float*)d_in[6];
    const float* scale_p  = (const float*)d_in[7];
    float* out = (float*)d_out;

    float *qb, *ob;
    cudaGetSymbolAddress((void**)&qb, g_q);
    cudaGetSymbolAddress((void**)&ob, g_o);

    dim3 gGemm(DIM / 64, MROWS / 64);   // 8 x 64 blocks

    // 1) q = x @ Wq^T
    sgemm_abt<<<gGemm, 256>>>(x, Wq, qb, MROWS, DIM, DIM);

    // 2) gather-attention (fused normalize + scale + softmax + AV)
    int nwarps = BATCH * HEADS * NCTX;            // 32768
    int threads = 256;
    int blocks = (nwarps * 32) / threads;         // 4096
    knn_attn<<<blocks, threads>>>(mem_db, knn_idx, mem_mask, scale_p);

    // 3) out = attn_out @ Wout^T
    sgemm_abt<<<gGemm, 256>>>(ob, Wout, out, MROWS, DIM, DIM);
}

// round 3
// speedup vs baseline: 1.3686x; 1.3686x over previous
#include <cuda_runtime.h>
#include <math.h>
#include <float.h>

#define BATCH 2
#define NCTX  2048
#define DIM   512
#define HEADS 8
#define DHEAD 64
#define KNN   32
#define MDB   131072
#define MROWS (BATCH*NCTX)   // 4096
#define TS    132            // smem row stride (pad: 16B-aligned, low conflict)

// scratch (device globals; no allocation allowed)
__device__ float g_q[MROWS * DIM];   // q raw, layout (b, n, h*d)
__device__ float g_o[MROWS * DIM];   // attention output, layout (b, n, h*d)

typedef unsigned long long ull;

#define FMA2(d, a, b) asm("fma.rn.f32x2 %0, %1, %2, %0;" : "+l"(d) : "l"(a), "l"(b))
#define DUP2(d, x)    asm("mov.b64 %0, {%1, %1};" : "=l"(d) : "r"(__float_as_uint(x)))

// ---------------------------------------------------------------------------
// C[M,N] = A[M,K] * B[N,K]^T  via packed f32x2 FMAs.
// BM=BN=128, BK=16, 256 threads, 8x8 microtile (4 row-pairs x 8 cols).
// M%128==0, N%128==0, K%16==0.
// ---------------------------------------------------------------------------
__global__ void __launch_bounds__(256) sgemm_abt_f2(
    const float* __restrict__ A,
    const float* __restrict__ Bm,
    float* __restrict__ C,
    int M, int N, int K)
{
    __shared__ __align__(16) float As[16 * TS];
    __shared__ __align__(16) float Bs[16 * TS];

    const int tid  = threadIdx.x;        // 0..255
    const int tx   = tid & 15;
    const int ty   = tid >> 4;
    const int row0 = blockIdx.y * 128;
    const int col0 = blockIdx.x * 128;

    // load mapping: 128 rows x 16 k = 512 float4; 2 per thread (rows lr, lr+64)
    const int lr = tid >> 2;             // 0..63
    const int lk = (tid & 3) << 2;       // 0,4,8,12

    const float* Ab = A  + (long)(row0 + lr) * K + lk;
    const float* Bb = Bm + (long)(col0 + lr) * K + lk;
    const long   skip = (long)64 * K;

    ull acc[4][8];
#pragma unroll
    for (int i = 0; i < 4; i++)
#pragma unroll
        for (int j = 0; j < 8; j++) acc[i][j] = 0ull;

    // prefetch tile 0
    float4 pa0 = *(const float4*)(Ab);
    float4 pa1 = *(const float4*)(Ab + skip);
    float4 pb0 = *(const float4*)(Bb);
    float4 pb1 = *(const float4*)(Bb + skip);

    const int NT = K / 16;
    for (int kt = 0; kt < NT; kt++) {
        // store staged tile to smem (k-major, padded)
        As[(lk + 0) * TS + lr]      = pa0.x;
        As[(lk + 1) * TS + lr]      = pa0.y;
        As[(lk + 2) * TS + lr]      = pa0.z;
        As[(lk + 3) * TS + lr]      = pa0.w;
        As[(lk + 0) * TS + lr + 64] = pa1.x;
        As[(lk + 1) * TS + lr + 64] = pa1.y;
        As[(lk + 2) * TS + lr + 64] = pa1.z;
        As[(lk + 3) * TS + lr + 64] = pa1.w;
        Bs[(lk + 0) * TS + lr]      = pb0.x;
        Bs[(lk + 1) * TS + lr]      = pb0.y;
        Bs[(lk + 2) * TS + lr]      = pb0.z;
        Bs[(lk + 3) * TS + lr]      = pb0.w;
        Bs[(lk + 0) * TS + lr + 64] = pb1.x;
        Bs[(lk + 1) * TS + lr + 64] = pb1.y;
        Bs[(lk + 2) * TS + lr + 64] = pb1.z;
        Bs[(lk + 3) * TS + lr + 64] = pb1.w;
        __syncthreads();

        // prefetch next tile while computing
        if (kt + 1 < NT) {
            int k0 = (kt + 1) * 16;
            pa0 = *(const float4*)(Ab + k0);
            pa1 = *(const float4*)(Ab + skip + k0);
            pb0 = *(const float4*)(Bb + k0);
            pb1 = *(const float4*)(Bb + skip + k0);
        }

#pragma unroll
        for (int kk = 0; kk < 16; kk++) {
            const float* ap = As + kk * TS + ty * 8;
            ull a0 = *(const ull*)(ap + 0);
            ull a1 = *(const ull*)(ap + 2);
            ull a2 = *(const ull*)(ap + 4);
            ull a3 = *(const ull*)(ap + 6);

            const float4* bp = (const float4*)(Bs + kk * TS + tx * 8);
            float4 b0 = bp[0];
            float4 b1 = bp[1];
            ull bd[8];
            DUP2(bd[0], b0.x); DUP2(bd[1], b0.y);
            DUP2(bd[2], b0.z); DUP2(bd[3], b0.w);
            DUP2(bd[4], b1.x); DUP2(bd[5], b1.y);
            DUP2(bd[6], b1.z); DUP2(bd[7], b1.w);

#pragma unroll
            for (int j = 0; j < 8; j++) {
                FMA2(acc[0][j], a0, bd[j]);
                FMA2(acc[1][j], a1, bd[j]);
                FMA2(acc[2][j], a2, bd[j]);
                FMA2(acc[3][j], a3, bd[j]);
            }
        }
        __syncthreads();
    }

    // epilogue: acc[ip][j] packs rows (ty*8+2ip, ty*8+2ip+1), col tx*8+j
#pragma unroll
    for (int ip = 0; ip < 4; ip++) {
        float2 v[8];
#pragma unroll
        for (int j = 0; j < 8; j++) v[j] = *(float2*)&acc[ip][j];
        int r = row0 + ty * 8 + 2 * ip;
        float* c0 = C + (long)r * N + col0 + tx * 8;
        float* c1 = c0 + N;
        *(float4*)(c0)     = make_float4(v[0].x, v[1].x, v[2].x, v[3].x);
        *(float4*)(c0 + 4) = make_float4(v[4].x, v[5].x, v[6].x, v[7].x);
        *(float4*)(c1)     = make_float4(v[0].y, v[1].y, v[2].y, v[3].y);
        *(float4*)(c1 + 4) = make_float4(v[4].y, v[5].y, v[6].y, v[7].y);
    }
}

// ---------------------------------------------------------------------------
// KNN attention: one warp per query (b, h, n). K=32 neighbors -> lane j owns
// neighbor j's sim/attn. q normalization + exp(scale) folded into q.
// mem_mask arrives as int32 (bool promoted by the harness).
// ---------------------------------------------------------------------------
__global__ void knn_attn(const float* __restrict__ mem_db,
                         const int*   __restrict__ knn_idx,
                         const int*   __restrict__ mem_mask,
                         const float* __restrict__ scale_param)
{
    const unsigned FULL = 0xffffffffu;
    int warp = (blockIdx.x * blockDim.x + threadIdx.x) >> 5;
    int lane = threadIdx.x & 31;
    if (warp >= BATCH * HEADS * NCTX) return;

    int n  = warp % NCTX;
    int bh = warp / NCTX;
    int h  = bh % HEADS;
    int b  = bh / HEADS;

    const float* qp = g_q + ((long)(b * NCTX + n) * DIM) + h * DHEAD;
    float q0 = qp[lane];
    float q1 = qp[lane + 32];

    float ss = q0 * q0 + q1 * q1;
#pragma unroll
    for (int o = 16; o > 0; o >>= 1) ss += __shfl_xor_sync(FULL, ss, o);
    float scale = expf(scale_param[h]);
    float inv = scale / fmaxf(sqrtf(ss), 1e-12f);
    q0 *= inv; q1 *= inv;

    long ib = (long)((b * HEADS + h) * NCTX + n) * KNN;
    int  idx = knn_idx[ib + lane];
    bool msk = mem_mask[ib + lane] != 0;

    const float* db = mem_db + (long)b * MDB * 2 * DHEAD;

    float sim = 0.f;
#pragma unroll
    for (int j = 0; j < KNN; j++) {
        int ij = __shfl_sync(FULL, idx, j);
        const float* kp = db + (long)ij * (2 * DHEAD);
        float p = fmaf(q0, kp[lane], q1 * kp[lane + 32]);
#pragma unroll
        for (int o = 16; o > 0; o >>= 1) p += __shfl_xor_sync(FULL, p, o);
        if (lane == j) sim = p;
    }

    sim = msk ? sim : -FLT_MAX;

    float m = sim;
#pragma unroll
    for (int o = 16; o > 0; o >>= 1) m = fmaxf(m, __shfl_xor_sync(FULL, m, o));
    float p = __expf(sim - m);
    float s = p;
#pragma unroll
    for (int o = 16; o > 0; o >>= 1) s += __shfl_xor_sync(FULL, s, o);
    float attn = p / s;

    float o0 = 0.f, o1 = 0.f;
#pragma unroll
    for (int j = 0; j < KNN; j++) {
        float a  = __shfl_sync(FULL, attn, j);
        int   ij = __shfl_sync(FULL, idx, j);
        const float* vp = db + (long)ij * (2 * DHEAD) + DHEAD;
        o0 = fmaf(a, vp[lane], o0);
        o1 = fmaf(a, vp[lane + 32], o1);
    }

    float* op = g_o + ((long)(b * NCTX + n) * DIM) + h * DHEAD;
    op[lane]      = o0;
    op[lane + 32] = o1;
}

// ---------------------------------------------------------------------------
extern "C" void kernel_launch(void* const* d_in, const int* in_sizes, int n_in,
                              void* d_out, int out_size)
{
    const float* x        = (const float*)d_in[0];
    const float* mem_db   = (const float*)d_in[1];
    const int*   knn_idx  = (const int*)d_in[2];
    const int*   mem_mask = (const int*)d_in[3];
    const float* Wq       = (const float*)d_in[4];
    // d_in[5] = Wkv : dead code in the reference, never used
    const float* Wout     = (const float*)d_in[6];
    const float* scale_p  = (const float*)d_in[7];
    float* out = (float*)d_out;

    float *qb, *ob;
    cudaGetSymbolAddress((void**)&qb, g_q);
    cudaGetSymbolAddress((void**)&ob, g_o);

    dim3 gGemm(DIM / 128, MROWS / 128);   // 4 x 32 = 128 blocks

    // 1) q = x @ Wq^T
    sgemm_abt_f2<<<gGemm, 256>>>(x, Wq, qb, MROWS, DIM, DIM);

    // 2) gather-attention (fused normalize + scale + softmax + AV)
    int nwarps = BATCH * HEADS * NCTX;            // 32768
    int threads = 256;
    int blocks = (nwarps * 32) / threads;         // 4096
    knn_attn<<<blocks, threads>>>(mem_db, knn_idx, mem_mask, scale_p);

    // 3) out = attn_out @ Wout^T
    sgemm_abt_f2<<<gGemm, 256>>>(ob, Wout, out, MROWS, DIM, DIM);
}

// round 5
// speedup vs baseline: 1.8975x; 1.3865x over previous
#include <cuda_runtime.h>
#include <cuda_bf16.h>
#include <math.h>
#include <float.h>
#include <stdint.h>

#define BATCH 2
#define NCTX  2048
#define DIM   512
#define HEADS 8
#define DHEAD 64
#define KNN   32
#define MDB   131072
#define MROWS (BATCH*NCTX)   // 4096
#define K2    (3*DIM)        // 1536: A'=[hi,hi,lo], B'=[hi,lo,hi]

// scratch (device globals; no allocation allowed)
__device__ float g_q[MROWS * DIM];
__device__ float g_o[MROWS * DIM];
__device__ __nv_bfloat16 g_a2[(size_t)MROWS * K2];  // 12 MB
__device__ __nv_bfloat16 g_b2[(size_t)DIM * K2];    // 1.5 MB

__device__ __forceinline__ uint32_t smem_u32(const void* p) {
    uint32_t a;
    asm("{ .reg .u64 t; cvta.to.shared.u64 t, %1; cvt.u32.u64 %0, t; }" : "=r"(a) : "l"(p));
    return a;
}
#define SW128(x) ((x) ^ (((x) >> 3) & 0x70))

#define LDSM_X4(r0, r1, r2, r3, addr) \
    asm volatile("ldmatrix.sync.aligned.m8n8.x4.shared.b16 {%0,%1,%2,%3}, [%4];" \
        : "=r"(r0), "=r"(r1), "=r"(r2), "=r"(r3) : "r"(addr))

#define MMA16816(c, a, b0, b1) \
    asm volatile("mma.sync.aligned.m16n8k16.row.col.f32.bf16.bf16.f32 " \
        "{%0,%1,%2,%3}, {%4,%5,%6,%7}, {%8,%9}, {%0,%1,%2,%3};" \
        : "+f"((c)[0]), "+f"((c)[1]), "+f"((c)[2]), "+f"((c)[3]) \
        : "r"((a)[0]), "r"((a)[1]), "r"((a)[2]), "r"((a)[3]), "r"(b0), "r"(b1))

// ---------------------------------------------------------------------------
// split: fp32 [rows, 512] -> bf16 [rows, 1536] with blocks hi@0, hi@ph, lo@pl
// ---------------------------------------------------------------------------
__global__ void split3(const float* __restrict__ in, __nv_bfloat16* __restrict__ out,
                       int rows, int ph, int pl)
{
    int idx = blockIdx.x * blockDim.x + threadIdx.x;
    if (idx >= rows * (DIM / 4)) return;
    int r  = idx / (DIM / 4);
    int c4 = (idx % (DIM / 4)) * 4;
    float4 v = *(const float4*)(in + (long)r * DIM + c4);

    float vv[4] = {v.x, v.y, v.z, v.w};
    unsigned long long hp = 0, lp = 0;
#pragma unroll
    for (int i = 0; i < 4; i++) {
        __nv_bfloat16 h = __float2bfloat16(vv[i]);
        __nv_bfloat16 l = __float2bfloat16(vv[i] - __bfloat162float(h));
        hp |= (unsigned long long)__bfloat16_as_ushort(h) << (16 * i);
        lp |= (unsigned long long)__bfloat16_as_ushort(l) << (16 * i);
    }
    __nv_bfloat16* base = out + (long)r * K2 + c4;
    *(unsigned long long*)(base)      = hp;
    *(unsigned long long*)(base + ph) = hp;
    *(unsigned long long*)(base + pl) = lp;
}

// ---------------------------------------------------------------------------
// bf16 mma.sync GEMM: C[M,N] = A2[M,K2] * B2[N,K2]^T, fp32 accum.
// CTA tile 128x128, 8 warps (2x4), warp tile 64x32, BK=64, double-buffered.
// grid = (N/128, M/128), 256 threads.
// ---------------------------------------------------------------------------
#define BKC   64
#define NCH   (K2 / BKC)          // 24
#define TILEB (128 * 128)         // 16 KB per tile (128 rows x 128 bytes)
#define SO_A0 0
#define SO_A1 TILEB
#define SO_B0 (2 * TILEB)
#define SO_B1 (3 * TILEB)
#define GSMEM (4 * TILEB)         // 64 KB

__global__ void __launch_bounds__(256, 1) gemm_mma(
    const __nv_bfloat16* __restrict__ A,
    const __nv_bfloat16* __restrict__ B,
    float* __restrict__ C, int N)
{
    extern __shared__ char smem[];
    uint32_t sb = smem_u32(smem);
    const int tid  = threadIdx.x;
    const int wid  = tid >> 5, lane = tid & 31;
    const int wr   = wid >> 2;          // 0..1  (m block of 64)
    const int wc   = wid & 3;           // 0..3  (n block of 32)
    const int row0 = blockIdx.y * 128, col0 = blockIdx.x * 128;

    // staging-copy mapping: 1024 x 16B per tile; 4 iters x 256 threads
    const int sr = tid >> 3;            // 0..31 base row
    const int sc = (tid & 7) * 16;      // byte col in 128B row

    // ldmatrix per-lane fixed offsets
    const uint32_t a_l = (uint32_t)((lane & 15) * 128 + ((lane >> 4) & 1) * 16);
    const uint32_t b_l = (uint32_t)(((lane & 7) + ((lane >> 4) & 1) * 8) * 128 + ((lane >> 3) & 1) * 16);

    const uint32_t aoff[2] = {SO_A0, SO_A1}, boff[2] = {SO_B0, SO_B1};

    float acc[4][4][4];
#pragma unroll
    for (int i = 0; i < 4; i++)
#pragma unroll
        for (int j = 0; j < 4; j++)
#pragma unroll
            for (int k = 0; k < 4; k++) acc[i][j][k] = 0.f;

    uint4 va[4], vb[4];
    // prologue: load + store chunk 0
#pragma unroll
    for (int i = 0; i < 4; i++) {
        int r = sr + i * 32;
        va[i] = *(const uint4*)(A + (long)(row0 + r) * K2 + (sc >> 1));
        vb[i] = *(const uint4*)(B + (long)(col0 + r) * K2 + (sc >> 1));
    }
#pragma unroll
    for (int i = 0; i < 4; i++) {
        int r = sr + i * 32;
        *(uint4*)(smem + SO_A0 + SW128(r * 128 + sc)) = va[i];
        *(uint4*)(smem + SO_B0 + SW128(r * 128 + sc)) = vb[i];
    }
    __syncthreads();

    for (int c = 0; c < NCH; c++) {
        int buf = c & 1;
        if (c + 1 < NCH) {
            int k0 = (c + 1) * BKC;
#pragma unroll
            for (int i = 0; i < 4; i++) {
                int r = sr + i * 32;
                va[i] = *(const uint4*)(A + (long)(row0 + r) * K2 + k0 + (sc >> 1));
                vb[i] = *(const uint4*)(B + (long)(col0 + r) * K2 + k0 + (sc >> 1));
            }
        }

        uint32_t sa  = sb + aoff[buf] + wr * (64 * 128);
        uint32_t sbm = sb + boff[buf] + wc * (32 * 128);

#pragma unroll
        for (int ks = 0; ks < 4; ks++) {
            // B fragments: 2 x ldmatrix.x4 cover 4 n-tiles of 8
            uint32_t bf[8];
#pragma unroll
            for (int np = 0; np < 2; np++) {
                uint32_t x = b_l + np * 2048 + ks * 32;
                LDSM_X4(bf[np * 4 + 0], bf[np * 4 + 1], bf[np * 4 + 2], bf[np * 4 + 3],
                        sbm + SW128(x));
            }
#pragma unroll
            for (int mt = 0; mt < 4; mt++) {
                uint32_t af[4];
                uint32_t x = a_l + mt * 2048 + ks * 32;
                LDSM_X4(af[0], af[1], af[2], af[3], sa + SW128(x));
#pragma unroll
                for (int nt = 0; nt < 4; nt++)
                    MMA16816(acc[mt][nt], af, bf[nt * 2], bf[nt * 2 + 1]);
            }
        }

        if (c + 1 < NCH) {
            int nb = (c + 1) & 1;
#pragma unroll
            for (int i = 0; i < 4; i++) {
                int r = sr + i * 32;
                *(uint4*)(smem + aoff[nb] + SW128(r * 128 + sc)) = va[i];
                *(uint4*)(smem + boff[nb] + SW128(r * 128 + sc)) = vb[i];
            }
        }
        __syncthreads();
    }

    // epilogue: acc[mt][nt] frag -> rows (lane/4, lane/4+8), cols (lane%4)*2
    const int qr = lane >> 2, qc = (lane & 3) * 2;
#pragma unroll
    for (int mt = 0; mt < 4; mt++) {
#pragma unroll
        for (int nt = 0; nt < 4; nt++) {
            int r = row0 + wr * 64 + mt * 16 + qr;
            int cc = col0 + wc * 32 + nt * 8 + qc;
            *(float2*)(C + (long)r * N + cc)       = make_float2(acc[mt][nt][0], acc[mt][nt][1]);
            *(float2*)(C + (long)(r + 8) * N + cc) = make_float2(acc[mt][nt][2], acc[mt][nt][3]);
        }
    }
}

// ---------------------------------------------------------------------------
// KNN attention: one warp per query (b, h, n). Unchanged (near LTS cap).
// ---------------------------------------------------------------------------
__global__ void knn_attn(const float* __restrict__ mem_db,
                         const int*   __restrict__ knn_idx,
                         const int*   __restrict__ mem_mask,
                         const float* __restrict__ scale_param)
{
    const unsigned FULL = 0xffffffffu;
    int warp = (blockIdx.x * blockDim.x + threadIdx.x) >> 5;
    int lane = threadIdx.x & 31;
    if (warp >= BATCH * HEADS * NCTX) return;

    int n  = warp % NCTX;
    int bh = warp / NCTX;
    int h  = bh % HEADS;
    int b  = bh / HEADS;

    const float* qp = g_q + ((long)(b * NCTX + n) * DIM) + h * DHEAD;
    float q0 = qp[lane];
    float q1 = qp[lane + 32];

    float ss = q0 * q0 + q1 * q1;
#pragma unroll
    for (int o = 16; o > 0; o >>= 1) ss += __shfl_xor_sync(FULL, ss, o);
    float scale = expf(scale_param[h]);
    float inv = scale / fmaxf(sqrtf(ss), 1e-12f);
    q0 *= inv; q1 *= inv;

    long ib = (long)((b * HEADS + h) * NCTX + n) * KNN;
    int  idx = knn_idx[ib + lane];
    bool msk = mem_mask[ib + lane] != 0;

    const float* db = mem_db + (long)b * MDB * 2 * DHEAD;

    float sim = 0.f;
#pragma unroll
    for (int j = 0; j < KNN; j++) {
        int ij = __shfl_sync(FULL, idx, j);
        const float* kp = db + (long)ij * (2 * DHEAD);
        float p = fmaf(q0, kp[lane], q1 * kp[lane + 32]);
#pragma unroll
        for (int o = 16; o > 0; o >>= 1) p += __shfl_xor_sync(FULL, p, o);
        if (lane == j) sim = p;
    }

    sim = msk ? sim : -FLT_MAX;

    float m = sim;
#pragma unroll
    for (int o = 16; o > 0; o >>= 1) m = fmaxf(m, __shfl_xor_sync(FULL, m, o));
    float p = __expf(sim - m);
    float s = p;
#pragma unroll
    for (int o = 16; o > 0; o >>= 1) s += __shfl_xor_sync(FULL, s, o);
    float attn = p / s;

    float o0 = 0.f, o1 = 0.f;
#pragma unroll
    for (int j = 0; j < KNN; j++) {
        float a  = __shfl_sync(FULL, attn, j);
        int   ij = __shfl_sync(FULL, idx, j);
        const float* vp = db + (long)ij * (2 * DHEAD) + DHEAD;
        o0 = fmaf(a, vp[lane], o0);
        o1 = fmaf(a, vp[lane + 32], o1);
    }

    float* op = g_o + ((long)(b * NCTX + n) * DIM) + h * DHEAD;
    op[lane]      = o0;
    op[lane + 32] = o1;
}

// ---------------------------------------------------------------------------
extern "C" void kernel_launch(void* const* d_in, const int* in_sizes, int n_in,
                              void* d_out, int out_size)
{
    const float* x        = (const float*)d_in[0];
    const float* mem_db   = (const float*)d_in[1];
    const int*   knn_idx  = (const int*)d_in[2];
    const int*   mem_mask = (const int*)d_in[3];
    const float* Wq       = (const float*)d_in[4];
    // d_in[5] = Wkv : dead code in the reference, never used
    const float* Wout     = (const float*)d_in[6];
    const float* scale_p  = (const float*)d_in[7];
    float* out = (float*)d_out;

    float *qb, *ob;
    __nv_bfloat16 *a2, *b2;
    cudaGetSymbolAddress((void**)&qb, g_q);
    cudaGetSymbolAddress((void**)&ob, g_o);
    cudaGetSymbolAddress((void**)&a2, g_a2);
    cudaGetSymbolAddress((void**)&b2, g_b2);

    cudaFuncSetAttribute(gemm_mma, cudaFuncAttributeMaxDynamicSharedMemorySize, GSMEM);

    dim3 gGemm(DIM / 128, MROWS / 128);   // (4, 32) = 128 CTAs
    const int splitA_blocks = (MROWS * (DIM / 4) + 255) / 256;  // 2048
    const int splitB_blocks = (DIM   * (DIM / 4) + 255) / 256;  // 256

    // 1) q = x @ Wq^T  (bf16x3 split tensor-core GEMM)
    split3<<<splitA_blocks, 256>>>(x, a2, MROWS, DIM, 2 * DIM);      // A: [hi, hi, lo]
    split3<<<splitB_blocks, 256>>>(Wq, b2, DIM, 2 * DIM, DIM);       // B: [hi, lo, hi]
    gemm_mma<<<gGemm, 256, GSMEM>>>(a2, b2, qb, DIM);

    // 2) gather-attention (fused normalize + scale + softmax + AV)
    int nwarps = BATCH * HEADS * NCTX;            // 32768
    knn_attn<<<(nwarps * 32) / 256, 256>>>(mem_db, knn_idx, mem_mask, scale_p);

    // 3) out = attn_out @ Wout^T
    split3<<<splitA_blocks, 256>>>(ob, a2, MROWS, DIM, 2 * DIM);
    split3<<<splitB_blocks, 256>>>(Wout, b2, DIM, 2 * DIM, DIM);
    gemm_mma<<<gGemm, 256, GSMEM>>>(a2, b2, out, DIM);
}